// round 2
// baseline (speedup 1.0000x reference)
#include <cuda_runtime.h>
#include <cuda_bf16.h>

#define N_NODES 10000
#define E_EDGES 160000
#define IN_CH   14
#define HID     128
#define HEADS   8
#define OUT_CH  4
#define FEAT    (HEADS*HID)   // 1024

// ---------------- scratch (static device memory; no allocations) ----------------
__device__ float g_bufA[(size_t)N_NODES * FEAT];
__device__ float g_bufB[(size_t)N_NODES * FEAT];
__device__ float g_als[N_NODES * HEADS];
__device__ float g_ald[N_NODES * HEADS];
__device__ float g_h3[N_NODES * OUT_CH];
__device__ float g_als3[N_NODES];
__device__ float g_ald3[N_NODES];
__device__ int   g_deg[N_NODES];
__device__ int   g_cursor[N_NODES];
__device__ int   g_rowptr[N_NODES + 1];
__device__ int   g_srcs[E_EDGES];
__device__ int   g_is64;

// ---------------- edge index access (int32 vs int64 detected at runtime) --------
__device__ __forceinline__ int edge_val(const void* idx, int is64, long i) {
    if (is64) return (int)((const long long*)idx)[i];
    return ((const int*)idx)[i];
}

__global__ void detect_kernel(const int* p) {
    if (threadIdx.x == 0 && blockIdx.x == 0) {
        int is64 = 1;
        for (int i = 0; i < 64; i++) {
            if (p[2*i + 1] != 0) { is64 = 0; break; }
        }
        g_is64 = is64;
    }
}

// ---------------- CSR build ----------------
__global__ void zero_kernel() {
    int i = blockIdx.x * blockDim.x + threadIdx.x;
    if (i < N_NODES) { g_deg[i] = 0; g_cursor[i] = 0; }
}

__global__ void count_kernel(const void* idx) {
    int e = blockIdx.x * blockDim.x + threadIdx.x;
    if (e < E_EDGES) {
        int f = g_is64;
        int d = edge_val(idx, f, (long)E_EDGES + e);
        atomicAdd(&g_deg[d], 1);
    }
}

__global__ void scan_kernel() {
    __shared__ int sums[1024];
    int t = threadIdx.x;
    const int CH = (N_NODES + 1023) / 1024;  // 10
    int base = t * CH;
    int s = 0;
    for (int i = 0; i < CH; i++) {
        int idx = base + i;
        if (idx < N_NODES) s += g_deg[idx];
    }
    sums[t] = s;
    __syncthreads();
    for (int off = 1; off < 1024; off <<= 1) {
        int v = (t >= off) ? sums[t - off] : 0;
        __syncthreads();
        sums[t] += v;
        __syncthreads();
    }
    int run = (t == 0) ? 0 : sums[t - 1];
    for (int i = 0; i < CH; i++) {
        int idx = base + i;
        if (idx < N_NODES) { g_rowptr[idx] = run; run += g_deg[idx]; }
    }
    if (t == 1023) g_rowptr[N_NODES] = run;
}

__global__ void scatter_kernel(const void* idx) {
    int e = blockIdx.x * blockDim.x + threadIdx.x;
    if (e < E_EDGES) {
        int f = g_is64;
        int s = edge_val(idx, f, e);
        int d = edge_val(idx, f, (long)E_EDGES + e);
        int pos = g_rowptr[d] + atomicAdd(&g_cursor[d], 1);
        g_srcs[pos] = s;
    }
}

// ---------------- Layer-1 GEMM: [N,14] @ [14,1024] ----------------
__global__ __launch_bounds__(256) void gemm1_kernel(const float* __restrict__ x,
                                                    const float* __restrict__ W1,
                                                    float* __restrict__ h) {
    __shared__ float xs[IN_CH];
    int n = blockIdx.x;
    int t = threadIdx.x;
    if (t < IN_CH) xs[t] = x[n * IN_CH + t];
    __syncthreads();
#pragma unroll
    for (int j = 0; j < 4; j++) {
        int c = t + j * 256;
        float acc = 0.f;
#pragma unroll
        for (int k = 0; k < IN_CH; k++) acc += xs[k] * W1[k * FEAT + c];
        h[(long)n * FEAT + c] = acc;
    }
}

// ---------------- attention logits: als/ald [N,8] ----------------
__global__ __launch_bounds__(256) void alpha_kernel(const float* __restrict__ h,
                                                    const float* __restrict__ asrc,
                                                    const float* __restrict__ adst,
                                                    float* __restrict__ als,
                                                    float* __restrict__ ald) {
    int n = blockIdx.x;
    int t = threadIdx.x, w = t >> 5, lane = t & 31;
    const float* hr = h + (long)n * FEAT + w * HID;
    float ss = 0.f, sd = 0.f;
#pragma unroll
    for (int c = lane; c < HID; c += 32) {
        float v = hr[c];
        ss += v * asrc[w * HID + c];
        sd += v * adst[w * HID + c];
    }
#pragma unroll
    for (int off = 16; off; off >>= 1) {
        ss += __shfl_xor_sync(~0u, ss, off);
        sd += __shfl_xor_sync(~0u, sd, off);
    }
    if (lane == 0) { als[n * HEADS + w] = ss; ald[n * HEADS + w] = sd; }
}

// ---------------- fused per-node softmax + aggregate (heads=8, C=128) -----------
__global__ __launch_bounds__(256) void agg_kernel(const float* __restrict__ h,
                                                  const float* __restrict__ als,
                                                  const float* __restrict__ ald,
                                                  const float* __restrict__ bias,
                                                  float* __restrict__ out) {
    int n = blockIdx.x;
    int t = threadIdx.x, w = t >> 5, lane = t & 31;
    __shared__ float s_m[HEADS], s_iz[HEADS];

    int start = g_rowptr[n];
    int cnt   = g_rowptr[n + 1] - start;   // self-loop added implicitly at i==cnt

    float aldn = ald[n * HEADS + w];
    // pass 1: max
    float mx = -1e30f;
    for (int i = lane; i <= cnt; i += 32) {
        int s = (i < cnt) ? g_srcs[start + i] : n;
        float e = als[s * HEADS + w] + aldn;
        e = e > 0.f ? e : 0.2f * e;
        mx = fmaxf(mx, e);
    }
#pragma unroll
    for (int off = 16; off; off >>= 1) mx = fmaxf(mx, __shfl_xor_sync(~0u, mx, off));
    // pass 2: sum of exp
    float z = 0.f;
    for (int i = lane; i <= cnt; i += 32) {
        int s = (i < cnt) ? g_srcs[start + i] : n;
        float e = als[s * HEADS + w] + aldn;
        e = e > 0.f ? e : 0.2f * e;
        z += expf(e - mx);
    }
#pragma unroll
    for (int off = 16; off; off >>= 1) z += __shfl_xor_sync(~0u, z, off);
    if (lane == 0) { s_m[w] = mx; s_iz[w] = 1.f / (z + 1e-16f); }
    __syncthreads();

    // pass 3: weighted accumulate (each thread: head w, 4 channels)
    float m = s_m[w], iz = s_iz[w];
    float4 acc = make_float4(0.f, 0.f, 0.f, 0.f);
    const int cbase = w * HID + lane * 4;
#pragma unroll 2
    for (int i = 0; i <= cnt; i++) {
        int s = (i < cnt) ? g_srcs[start + i] : n;
        float e = als[s * HEADS + w] + aldn;
        e = e > 0.f ? e : 0.2f * e;
        float alpha = expf(e - m) * iz;
        float4 hv = *(const float4*)&h[(long)s * FEAT + cbase];
        acc.x += alpha * hv.x; acc.y += alpha * hv.y;
        acc.z += alpha * hv.z; acc.w += alpha * hv.w;
    }
    float4 b4 = *(const float4*)&bias[cbase];
    acc.x = fmaxf(acc.x + b4.x, 0.f);
    acc.y = fmaxf(acc.y + b4.y, 0.f);
    acc.z = fmaxf(acc.z + b4.z, 0.f);
    acc.w = fmaxf(acc.w + b4.w, 0.f);
    *(float4*)&out[(long)n * FEAT + cbase] = acc;
}

// ---------------- big SGEMM: [M,K] @ [K,Nn] fp32 (layer 2) ----------------
#define BM 128
#define BN 128
#define BK 8
#define TM 8
#define TN 8
__global__ __launch_bounds__(256) void sgemm_kernel(const float* __restrict__ A,
                                                    const float* __restrict__ B,
                                                    float* __restrict__ C,
                                                    int M, int Nn, int K) {
    __shared__ float As[BK][BM];
    __shared__ float Bs[BK][BN];
    int tid = threadIdx.x;
    int row0 = blockIdx.y * BM, col0 = blockIdx.x * BN;
    int tr = tid / (BN / TN);     // 0..15
    int tc = tid % (BN / TN);     // 0..15
    float acc[TM][TN] = {};
    int aRow = tid >> 1;          // 0..127
    int aCol = (tid & 1) * 4;     // 0 or 4
    int bRow = tid >> 5;          // 0..7
    int bCol = (tid & 31) * 4;    // 0..124

    for (int k0 = 0; k0 < K; k0 += BK) {
        float4 a4;
        int gr = row0 + aRow;
        if (gr < M) a4 = *(const float4*)&A[(long)gr * K + k0 + aCol];
        else        a4 = make_float4(0.f, 0.f, 0.f, 0.f);
        As[aCol + 0][aRow] = a4.x;
        As[aCol + 1][aRow] = a4.y;
        As[aCol + 2][aRow] = a4.z;
        As[aCol + 3][aRow] = a4.w;
        float4 b4 = *(const float4*)&B[(long)(k0 + bRow) * Nn + col0 + bCol];
        *(float4*)&Bs[bRow][bCol] = b4;
        __syncthreads();
#pragma unroll
        for (int k = 0; k < BK; k++) {
            float ra[TM], rb[TN];
#pragma unroll
            for (int i = 0; i < TM; i++) ra[i] = As[k][tr * TM + i];
#pragma unroll
            for (int j = 0; j < TN; j++) rb[j] = Bs[k][tc * TN + j];
#pragma unroll
            for (int i = 0; i < TM; i++)
#pragma unroll
                for (int j = 0; j < TN; j++) acc[i][j] += ra[i] * rb[j];
        }
        __syncthreads();
    }
#pragma unroll
    for (int i = 0; i < TM; i++) {
        int gr = row0 + tr * TM + i;
        if (gr < M) {
#pragma unroll
            for (int j = 0; j < TN; j += 4) {
                float4 v = make_float4(acc[i][j], acc[i][j+1], acc[i][j+2], acc[i][j+3]);
                *(float4*)&C[(long)gr * Nn + col0 + tc * TN + j] = v;
            }
        }
    }
}

// ---------------- layer-3 GEMM + logits (warp per node) ----------------
__global__ __launch_bounds__(256) void gemm3_kernel(const float* __restrict__ h,
                                                    const float* __restrict__ W3,
                                                    const float* __restrict__ as3,
                                                    const float* __restrict__ ad3) {
    int gw = (blockIdx.x * blockDim.x + threadIdx.x) >> 5;
    int lane = threadIdx.x & 31;
    if (gw >= N_NODES) return;
    const float* hr = h + (long)gw * FEAT;
    float a0 = 0.f, a1 = 0.f, a2 = 0.f, a3 = 0.f;
    for (int k = lane; k < FEAT; k += 32) {
        float v = hr[k];
        a0 += v * W3[k * 4 + 0];
        a1 += v * W3[k * 4 + 1];
        a2 += v * W3[k * 4 + 2];
        a3 += v * W3[k * 4 + 3];
    }
#pragma unroll
    for (int off = 16; off; off >>= 1) {
        a0 += __shfl_xor_sync(~0u, a0, off);
        a1 += __shfl_xor_sync(~0u, a1, off);
        a2 += __shfl_xor_sync(~0u, a2, off);
        a3 += __shfl_xor_sync(~0u, a3, off);
    }
    if (lane == 0) {
        g_h3[gw * 4 + 0] = a0; g_h3[gw * 4 + 1] = a1;
        g_h3[gw * 4 + 2] = a2; g_h3[gw * 4 + 3] = a3;
        g_als3[gw] = a0 * as3[0] + a1 * as3[1] + a2 * as3[2] + a3 * as3[3];
        g_ald3[gw] = a0 * ad3[0] + a1 * ad3[1] + a2 * ad3[2] + a3 * ad3[3];
    }
}

// ---------------- layer-3 aggregation (warp per node, 1 head, C=4) --------------
__global__ __launch_bounds__(256) void agg3_kernel(const float* __restrict__ b3,
                                                   float* __restrict__ out) {
    int n = (blockIdx.x * blockDim.x + threadIdx.x) >> 5;
    int lane = threadIdx.x & 31;
    if (n >= N_NODES) return;
    int start = g_rowptr[n];
    int cnt   = g_rowptr[n + 1] - start;
    float aldn = g_ald3[n];
    float mx = -1e30f;
    for (int i = lane; i <= cnt; i += 32) {
        int s = (i < cnt) ? g_srcs[start + i] : n;
        float e = g_als3[s] + aldn;
        e = e > 0.f ? e : 0.2f * e;
        mx = fmaxf(mx, e);
    }
#pragma unroll
    for (int off = 16; off; off >>= 1) mx = fmaxf(mx, __shfl_xor_sync(~0u, mx, off));
    float z = 0.f;
    for (int i = lane; i <= cnt; i += 32) {
        int s = (i < cnt) ? g_srcs[start + i] : n;
        float e = g_als3[s] + aldn;
        e = e > 0.f ? e : 0.2f * e;
        z += expf(e - mx);
    }
#pragma unroll
    for (int off = 16; off; off >>= 1) z += __shfl_xor_sync(~0u, z, off);
    float iz = 1.f / (z + 1e-16f);
    float c0 = 0.f, c1 = 0.f, c2 = 0.f, c3 = 0.f;
    for (int i = lane; i <= cnt; i += 32) {
        int s = (i < cnt) ? g_srcs[start + i] : n;
        float e = g_als3[s] + aldn;
        e = e > 0.f ? e : 0.2f * e;
        float alpha = expf(e - mx) * iz;
        c0 += alpha * g_h3[s * 4 + 0];
        c1 += alpha * g_h3[s * 4 + 1];
        c2 += alpha * g_h3[s * 4 + 2];
        c3 += alpha * g_h3[s * 4 + 3];
    }
#pragma unroll
    for (int off = 16; off; off >>= 1) {
        c0 += __shfl_xor_sync(~0u, c0, off);
        c1 += __shfl_xor_sync(~0u, c1, off);
        c2 += __shfl_xor_sync(~0u, c2, off);
        c3 += __shfl_xor_sync(~0u, c3, off);
    }
    if (lane == 0) {
        out[n * 4 + 0] = fmaxf(c0 + b3[0], 0.f);
        out[n * 4 + 1] = fmaxf(c1 + b3[1], 0.f);
        out[n * 4 + 2] = fmaxf(c2 + b3[2], 0.f);
        out[n * 4 + 3] = fmaxf(c3 + b3[3], 0.f);
    }
}

// ---------------- launch ----------------
extern "C" void kernel_launch(void* const* d_in, const int* in_sizes, int n_in,
                              void* d_out, int out_size) {
    const float* x      = (const float*)d_in[0];
    const void*  eidx   = d_in[1];
    const float* W1     = (const float*)d_in[2];
    const float* a_src1 = (const float*)d_in[3];
    const float* a_dst1 = (const float*)d_in[4];
    const float* b1     = (const float*)d_in[5];
    const float* W2     = (const float*)d_in[6];
    const float* a_src2 = (const float*)d_in[7];
    const float* a_dst2 = (const float*)d_in[8];
    const float* b2     = (const float*)d_in[9];
    const float* W3     = (const float*)d_in[10];
    const float* a_src3 = (const float*)d_in[11];
    const float* a_dst3 = (const float*)d_in[12];
    const float* b3     = (const float*)d_in[13];
    float* out = (float*)d_out;

    float* bufA; cudaGetSymbolAddress((void**)&bufA, g_bufA);
    float* bufB; cudaGetSymbolAddress((void**)&bufB, g_bufB);
    float* als;  cudaGetSymbolAddress((void**)&als,  g_als);
    float* ald;  cudaGetSymbolAddress((void**)&ald,  g_ald);
    float* h3;   cudaGetSymbolAddress((void**)&h3,   g_h3);

    // edge-index width detection + CSR build
    detect_kernel<<<1, 32>>>((const int*)eidx);
    zero_kernel<<<(N_NODES + 255) / 256, 256>>>();
    count_kernel<<<(E_EDGES + 255) / 256, 256>>>(eidx);
    scan_kernel<<<1, 1024>>>();
    scatter_kernel<<<(E_EDGES + 255) / 256, 256>>>(eidx);

    // layer 1
    gemm1_kernel<<<N_NODES, 256>>>(x, W1, bufA);
    alpha_kernel<<<N_NODES, 256>>>(bufA, a_src1, a_dst1, als, ald);
    agg_kernel<<<N_NODES, 256>>>(bufA, als, ald, b1, bufB);

    // layer 2
    dim3 g2(FEAT / BN, (N_NODES + BM - 1) / BM);
    sgemm_kernel<<<g2, 256>>>(bufB, W2, bufA, N_NODES, FEAT, FEAT);
    alpha_kernel<<<N_NODES, 256>>>(bufA, a_src2, a_dst2, als, ald);
    agg_kernel<<<N_NODES, 256>>>(bufA, als, ald, b2, bufB);

    // layer 3
    gemm3_kernel<<<(N_NODES * 32 + 255) / 256, 256>>>(bufB, W3, a_src3, a_dst3);
    agg3_kernel<<<(N_NODES * 32 + 255) / 256, 256>>>(b3, out);
}

// round 4
// speedup vs baseline: 2.0552x; 2.0552x over previous
#include <cuda_runtime.h>
#include <cuda_bf16.h>
#include <cstdint>

#define N_NODES 10000
#define E_EDGES 160000
#define IN_CH   14
#define HID     128
#define HEADS   8
#define OUT_CH  4
#define FEAT    (HEADS*HID)   // 1024

// ---------------- scratch (static device memory; no allocations) ----------------
__device__ float g_bufA[(size_t)N_NODES * FEAT];
__device__ float g_bufB[(size_t)N_NODES * FEAT];
__device__ float g_W2T[(size_t)FEAT * FEAT];
__device__ float g_als[N_NODES * HEADS];
__device__ float g_ald[N_NODES * HEADS];
__device__ float g_h3[N_NODES * OUT_CH];
__device__ float g_als3[N_NODES];
__device__ float g_ald3[N_NODES];
__device__ int   g_deg[N_NODES];
__device__ int   g_cursor[N_NODES];
__device__ int   g_rowptr[N_NODES + 1];
__device__ int   g_srcs[E_EDGES];
__device__ int   g_is64;

// ---------------- small PTX helpers ----------------
__device__ __forceinline__ uint32_t smem_u32(const void* p) {
    uint32_t a;
    asm("{ .reg .u64 t; cvta.to.shared.u64 t, %1; cvt.u32.u64 %0, t; }" : "=r"(a) : "l"(p));
    return a;
}

__device__ __forceinline__ void cp_async16(uint32_t s, const void* g, bool pred) {
    int sz = pred ? 16 : 0;
    asm volatile("cp.async.cg.shared.global [%0], [%1], 16, %2;\n"
                 :: "r"(s), "l"(g), "r"(sz) : "memory");
}
#define CP_COMMIT()  asm volatile("cp.async.commit_group;" ::: "memory")
#define CP_WAIT0()   asm volatile("cp.async.wait_group 0;" ::: "memory")

__device__ __forceinline__ uint32_t f2tf32(float f) {
    uint32_t r;
    asm("cvt.rna.tf32.f32 %0, %1;" : "=r"(r) : "f"(f));
    return r;
}

__device__ __forceinline__ void mma_tf32(float* c, const uint32_t* a, uint32_t b0, uint32_t b1) {
    asm volatile(
        "mma.sync.aligned.m16n8k8.row.col.f32.tf32.tf32.f32 "
        "{%0,%1,%2,%3}, {%4,%5,%6,%7}, {%8,%9}, {%0,%1,%2,%3};"
        : "+f"(c[0]), "+f"(c[1]), "+f"(c[2]), "+f"(c[3])
        : "r"(a[0]), "r"(a[1]), "r"(a[2]), "r"(a[3]), "r"(b0), "r"(b1));
}

// ---------------- edge index access (int32 vs int64 detected at runtime) --------
__device__ __forceinline__ int edge_val(const void* idx, int is64, long i) {
    if (is64) return (int)((const long long*)idx)[i];
    return ((const int*)idx)[i];
}

__global__ void detect_kernel(const int* p) {
    if (threadIdx.x == 0 && blockIdx.x == 0) {
        int is64 = 1;
        for (int i = 0; i < 64; i++) {
            if (p[2*i + 1] != 0) { is64 = 0; break; }
        }
        g_is64 = is64;
    }
}

// ---------------- CSR build ----------------
__global__ void zero_kernel() {
    int i = blockIdx.x * blockDim.x + threadIdx.x;
    if (i < N_NODES) { g_deg[i] = 0; g_cursor[i] = 0; }
}

__global__ void count_kernel(const void* idx) {
    int e = blockIdx.x * blockDim.x + threadIdx.x;
    if (e < E_EDGES) {
        int f = g_is64;
        int d = edge_val(idx, f, (long)E_EDGES + e);
        atomicAdd(&g_deg[d], 1);
    }
}

__global__ void scan_kernel() {
    __shared__ int sums[1024];
    int t = threadIdx.x;
    const int CH = (N_NODES + 1023) / 1024;
    int base = t * CH;
    int s = 0;
    for (int i = 0; i < CH; i++) {
        int idx = base + i;
        if (idx < N_NODES) s += g_deg[idx];
    }
    sums[t] = s;
    __syncthreads();
    for (int off = 1; off < 1024; off <<= 1) {
        int v = (t >= off) ? sums[t - off] : 0;
        __syncthreads();
        sums[t] += v;
        __syncthreads();
    }
    int run = (t == 0) ? 0 : sums[t - 1];
    for (int i = 0; i < CH; i++) {
        int idx = base + i;
        if (idx < N_NODES) { g_rowptr[idx] = run; run += g_deg[idx]; }
    }
    if (t == 1023) g_rowptr[N_NODES] = run;
}

__global__ void scatter_kernel(const void* idx) {
    int e = blockIdx.x * blockDim.x + threadIdx.x;
    if (e < E_EDGES) {
        int f = g_is64;
        int s = edge_val(idx, f, e);
        int d = edge_val(idx, f, (long)E_EDGES + e);
        int pos = g_rowptr[d] + atomicAdd(&g_cursor[d], 1);
        g_srcs[pos] = s;
    }
}

// ---------------- Layer-1 GEMM: [N,14] @ [14,1024], 16 nodes per block -----------
#define G1N 16
__global__ __launch_bounds__(256) void gemm1_kernel(const float* __restrict__ x,
                                                    const float* __restrict__ W1,
                                                    float* __restrict__ h) {
    __shared__ float xs[G1N * IN_CH];
    int nb = blockIdx.x * G1N;
    int t = threadIdx.x;
    if (t < G1N * IN_CH) xs[t] = x[nb * IN_CH + t];
    __syncthreads();
#pragma unroll
    for (int j = 0; j < 4; j++) {
        int c = t + j * 256;
        float w[IN_CH];
#pragma unroll
        for (int k = 0; k < IN_CH; k++) w[k] = W1[k * FEAT + c];
        for (int n = 0; n < G1N; n++) {
            float acc = 0.f;
#pragma unroll
            for (int k = 0; k < IN_CH; k++) acc += xs[n * IN_CH + k] * w[k];
            h[(size_t)(nb + n) * FEAT + c] = acc;
        }
    }
}

// ---------------- W2 transpose: W2T[n][k] = W2[k][n] ----------------
__global__ __launch_bounds__(256) void transpose_kernel(const float* __restrict__ W,
                                                        float* __restrict__ WT) {
    __shared__ float t[32][33];
    int bx = blockIdx.x * 32, by = blockIdx.y * 32;
    int x = bx + threadIdx.x;
    int y = by + threadIdx.y;
#pragma unroll
    for (int j = 0; j < 32; j += 8) t[threadIdx.y + j][threadIdx.x] = W[(size_t)(y + j) * FEAT + x];
    __syncthreads();
    int x2 = by + threadIdx.x;
    int y2 = bx + threadIdx.y;
#pragma unroll
    for (int j = 0; j < 32; j += 8) WT[(size_t)(y2 + j) * FEAT + x2] = t[threadIdx.x][threadIdx.y + j];
}

// ---------------- attention logits: als/ald [N,8] ----------------
__global__ __launch_bounds__(256) void alpha_kernel(const float* __restrict__ h,
                                                    const float* __restrict__ asrc,
                                                    const float* __restrict__ adst,
                                                    float* __restrict__ als,
                                                    float* __restrict__ ald) {
    int n = blockIdx.x;
    int t = threadIdx.x, w = t >> 5, lane = t & 31;
    const float* hr = h + (size_t)n * FEAT + w * HID;
    float ss = 0.f, sd = 0.f;
#pragma unroll
    for (int c = lane; c < HID; c += 32) {
        float v = hr[c];
        ss += v * asrc[w * HID + c];
        sd += v * adst[w * HID + c];
    }
#pragma unroll
    for (int off = 16; off; off >>= 1) {
        ss += __shfl_xor_sync(~0u, ss, off);
        sd += __shfl_xor_sync(~0u, sd, off);
    }
    if (lane == 0) { als[n * HEADS + w] = ss; ald[n * HEADS + w] = sd; }
}

// ---------------- fused per-node softmax + aggregate (heads=8, C=128) -----------
__global__ __launch_bounds__(256) void agg_kernel(const float* __restrict__ h,
                                                  const float* __restrict__ als,
                                                  const float* __restrict__ ald,
                                                  const float* __restrict__ bias,
                                                  float* __restrict__ out) {
    int n = blockIdx.x;
    int t = threadIdx.x, w = t >> 5, lane = t & 31;
    __shared__ float s_m[HEADS], s_iz[HEADS];

    int start = g_rowptr[n];
    int cnt   = g_rowptr[n + 1] - start;   // self-loop added implicitly at i==cnt

    float aldn = ald[n * HEADS + w];
    float mx = -1e30f;
    for (int i = lane; i <= cnt; i += 32) {
        int s = (i < cnt) ? g_srcs[start + i] : n;
        float e = als[s * HEADS + w] + aldn;
        e = e > 0.f ? e : 0.2f * e;
        mx = fmaxf(mx, e);
    }
#pragma unroll
    for (int off = 16; off; off >>= 1) mx = fmaxf(mx, __shfl_xor_sync(~0u, mx, off));
    float z = 0.f;
    for (int i = lane; i <= cnt; i += 32) {
        int s = (i < cnt) ? g_srcs[start + i] : n;
        float e = als[s * HEADS + w] + aldn;
        e = e > 0.f ? e : 0.2f * e;
        z += expf(e - mx);
    }
#pragma unroll
    for (int off = 16; off; off >>= 1) z += __shfl_xor_sync(~0u, z, off);
    if (lane == 0) { s_m[w] = mx; s_iz[w] = 1.f / (z + 1e-16f); }
    __syncthreads();

    float m = s_m[w], iz = s_iz[w];
    float4 acc = make_float4(0.f, 0.f, 0.f, 0.f);
    const int cbase = w * HID + lane * 4;
#pragma unroll 2
    for (int i = 0; i <= cnt; i++) {
        int s = (i < cnt) ? g_srcs[start + i] : n;
        float e = als[s * HEADS + w] + aldn;
        e = e > 0.f ? e : 0.2f * e;
        float alpha = expf(e - m) * iz;
        float4 hv = *(const float4*)&h[(size_t)s * FEAT + cbase];
        acc.x += alpha * hv.x; acc.y += alpha * hv.y;
        acc.z += alpha * hv.z; acc.w += alpha * hv.w;
    }
    float4 b4 = *(const float4*)&bias[cbase];
    acc.x = fmaxf(acc.x + b4.x, 0.f);
    acc.y = fmaxf(acc.y + b4.y, 0.f);
    acc.z = fmaxf(acc.z + b4.z, 0.f);
    acc.w = fmaxf(acc.w + b4.w, 0.f);
    *(float4*)&out[(size_t)n * FEAT + cbase] = acc;
}

// ---------------- tf32 mma.sync GEMM: C[M,1024] = A[M,1024] @ W2, BT[n][k] -------
// CTA 128x128, BK=32, 8 warps each 64x32, double-buffered cp.async smem pipeline.
#define LDA  36                       // floats per smem row (32 + 4 pad)
#define TBUF (128 * LDA * 4)          // bytes per tile (18432)
#define BUFB (2 * TBUF)               // A+B per stage (36864)
#define NIT  32                       // 1024 / 32

__device__ __forceinline__ void load_tiles_async(
    const float* __restrict__ A, const float* __restrict__ BT,
    uint32_t sA, uint32_t sB, int row0, int n0, int k0, int M, int tid)
{
#pragma unroll
    for (int j = 0; j < 4; j++) {
        int f = tid + j * 256;            // 0..1023
        int r = f >> 3;                   // 0..127
        int c = f & 7;                    // float4 chunk
        uint32_t so = (uint32_t)(r * LDA + c * 4) * 4;
        bool ok = (row0 + r) < M;
        int ar = ok ? (row0 + r) : 0;
        cp_async16(sA + so, A  + (size_t)ar * FEAT + k0 + c * 4, ok);
        cp_async16(sB + so, BT + (size_t)(n0 + r) * FEAT + k0 + c * 4, true);
    }
}

__global__ __launch_bounds__(256) void tf32_gemm_kernel(
    const float* __restrict__ A, const float* __restrict__ BT,
    float* __restrict__ C, int M)
{
    extern __shared__ char dsm[];
    const uint32_t sbase = smem_u32(dsm);
    int tid = threadIdx.x;
    int wid = tid >> 5, lane = tid & 31;
    int grp = lane >> 2, tig = lane & 3;
    int wm = (wid & 1) * 64;
    int wn = (wid >> 1) * 32;
    int row0 = blockIdx.y * 128, n0 = blockIdx.x * 128;

    float acc[4][4][4];
#pragma unroll
    for (int i = 0; i < 4; i++)
#pragma unroll
        for (int j = 0; j < 4; j++)
#pragma unroll
            for (int k = 0; k < 4; k++) acc[i][j][k] = 0.f;

    load_tiles_async(A, BT, sbase, sbase + TBUF, row0, n0, 0, M, tid);
    CP_COMMIT();

    for (int it = 0; it < NIT; it++) {
        CP_WAIT0();
        __syncthreads();
        int cb = it & 1;
        if (it + 1 < NIT) {
            uint32_t nb = sbase + (cb ^ 1) * BUFB;
            load_tiles_async(A, BT, nb, nb + TBUF, row0, n0, (it + 1) * 32, M, tid);
            CP_COMMIT();
        }
        const float* As = (const float*)(dsm + cb * BUFB);
        const float* Bs = (const float*)(dsm + cb * BUFB + TBUF);
#pragma unroll
        for (int ks = 0; ks < 4; ks++) {
            int kk = ks * 8 + tig;
            uint32_t a[4][4];
#pragma unroll
            for (int mt = 0; mt < 4; mt++) {
                int r0 = wm + mt * 16 + grp;
                a[mt][0] = f2tf32(As[r0 * LDA + kk]);
                a[mt][1] = f2tf32(As[(r0 + 8) * LDA + kk]);
                a[mt][2] = f2tf32(As[r0 * LDA + kk + 4]);
                a[mt][3] = f2tf32(As[(r0 + 8) * LDA + kk + 4]);
            }
#pragma unroll
            for (int nt = 0; nt < 4; nt++) {
                int rn = wn + nt * 8 + grp;
                uint32_t b0 = f2tf32(Bs[rn * LDA + kk]);
                uint32_t b1 = f2tf32(Bs[rn * LDA + kk + 4]);
#pragma unroll
                for (int mt = 0; mt < 4; mt++) mma_tf32(acc[mt][nt], a[mt], b0, b1);
            }
        }
        __syncthreads();
    }

    // epilogue
#pragma unroll
    for (int mt = 0; mt < 4; mt++) {
        int gr = row0 + wm + mt * 16 + grp;
#pragma unroll
        for (int nt = 0; nt < 4; nt++) {
            int gc = n0 + wn + nt * 8 + 2 * tig;
            if (gr < M) {
                float2 v0 = make_float2(acc[mt][nt][0], acc[mt][nt][1]);
                *(float2*)&C[(size_t)gr * FEAT + gc] = v0;
            }
            if (gr + 8 < M) {
                float2 v1 = make_float2(acc[mt][nt][2], acc[mt][nt][3]);
                *(float2*)&C[(size_t)(gr + 8) * FEAT + gc] = v1;
            }
        }
    }
}

// ---------------- layer-3 GEMM + logits (warp per node) ----------------
__global__ __launch_bounds__(256) void gemm3_kernel(const float* __restrict__ h,
                                                    const float* __restrict__ W3,
                                                    const float* __restrict__ as3,
                                                    const float* __restrict__ ad3) {
    int gw = (blockIdx.x * blockDim.x + threadIdx.x) >> 5;
    int lane = threadIdx.x & 31;
    if (gw >= N_NODES) return;
    const float* hr = h + (size_t)gw * FEAT;
    float a0 = 0.f, a1 = 0.f, a2 = 0.f, a3 = 0.f;
    for (int k = lane; k < FEAT; k += 32) {
        float v = hr[k];
        a0 += v * W3[k * 4 + 0];
        a1 += v * W3[k * 4 + 1];
        a2 += v * W3[k * 4 + 2];
        a3 += v * W3[k * 4 + 3];
    }
#pragma unroll
    for (int off = 16; off; off >>= 1) {
        a0 += __shfl_xor_sync(~0u, a0, off);
        a1 += __shfl_xor_sync(~0u, a1, off);
        a2 += __shfl_xor_sync(~0u, a2, off);
        a3 += __shfl_xor_sync(~0u, a3, off);
    }
    if (lane == 0) {
        g_h3[gw * 4 + 0] = a0; g_h3[gw * 4 + 1] = a1;
        g_h3[gw * 4 + 2] = a2; g_h3[gw * 4 + 3] = a3;
        g_als3[gw] = a0 * as3[0] + a1 * as3[1] + a2 * as3[2] + a3 * as3[3];
        g_ald3[gw] = a0 * ad3[0] + a1 * ad3[1] + a2 * ad3[2] + a3 * ad3[3];
    }
}

// ---------------- layer-3 aggregation (warp per node, 1 head, C=4) --------------
__global__ __launch_bounds__(256) void agg3_kernel(const float* __restrict__ b3,
                                                   float* __restrict__ out) {
    int n = (blockIdx.x * blockDim.x + threadIdx.x) >> 5;
    int lane = threadIdx.x & 31;
    if (n >= N_NODES) return;
    int start = g_rowptr[n];
    int cnt   = g_rowptr[n + 1] - start;
    float aldn = g_ald3[n];
    float mx = -1e30f;
    for (int i = lane; i <= cnt; i += 32) {
        int s = (i < cnt) ? g_srcs[start + i] : n;
        float e = g_als3[s] + aldn;
        e = e > 0.f ? e : 0.2f * e;
        mx = fmaxf(mx, e);
    }
#pragma unroll
    for (int off = 16; off; off >>= 1) mx = fmaxf(mx, __shfl_xor_sync(~0u, mx, off));
    float z = 0.f;
    for (int i = lane; i <= cnt; i += 32) {
        int s = (i < cnt) ? g_srcs[start + i] : n;
        float e = g_als3[s] + aldn;
        e = e > 0.f ? e : 0.2f * e;
        z += expf(e - mx);
    }
#pragma unroll
    for (int off = 16; off; off >>= 1) z += __shfl_xor_sync(~0u, z, off);
    float iz = 1.f / (z + 1e-16f);
    float c0 = 0.f, c1 = 0.f, c2 = 0.f, c3 = 0.f;
    for (int i = lane; i <= cnt; i += 32) {
        int s = (i < cnt) ? g_srcs[start + i] : n;
        float e = g_als3[s] + aldn;
        e = e > 0.f ? e : 0.2f * e;
        float alpha = expf(e - mx) * iz;
        c0 += alpha * g_h3[s * 4 + 0];
        c1 += alpha * g_h3[s * 4 + 1];
        c2 += alpha * g_h3[s * 4 + 2];
        c3 += alpha * g_h3[s * 4 + 3];
    }
#pragma unroll
    for (int off = 16; off; off >>= 1) {
        c0 += __shfl_xor_sync(~0u, c0, off);
        c1 += __shfl_xor_sync(~0u, c1, off);
        c2 += __shfl_xor_sync(~0u, c2, off);
        c3 += __shfl_xor_sync(~0u, c3, off);
    }
    if (lane == 0) {
        out[n * 4 + 0] = fmaxf(c0 + b3[0], 0.f);
        out[n * 4 + 1] = fmaxf(c1 + b3[1], 0.f);
        out[n * 4 + 2] = fmaxf(c2 + b3[2], 0.f);
        out[n * 4 + 3] = fmaxf(c3 + b3[3], 0.f);
    }
}

// ---------------- launch ----------------
extern "C" void kernel_launch(void* const* d_in, const int* in_sizes, int n_in,
                              void* d_out, int out_size) {
    const float* x      = (const float*)d_in[0];
    const void*  eidx   = d_in[1];
    const float* W1     = (const float*)d_in[2];
    const float* a_src1 = (const float*)d_in[3];
    const float* a_dst1 = (const float*)d_in[4];
    const float* b1     = (const float*)d_in[5];
    const float* W2     = (const float*)d_in[6];
    const float* a_src2 = (const float*)d_in[7];
    const float* a_dst2 = (const float*)d_in[8];
    const float* b2     = (const float*)d_in[9];
    const float* W3     = (const float*)d_in[10];
    const float* a_src3 = (const float*)d_in[11];
    const float* a_dst3 = (const float*)d_in[12];
    const float* b3     = (const float*)d_in[13];
    float* out = (float*)d_out;

    float* bufA; cudaGetSymbolAddress((void**)&bufA, g_bufA);
    float* bufB; cudaGetSymbolAddress((void**)&bufB, g_bufB);
    float* w2t;  cudaGetSymbolAddress((void**)&w2t,  g_W2T);
    float* als;  cudaGetSymbolAddress((void**)&als,  g_als);
    float* ald;  cudaGetSymbolAddress((void**)&ald,  g_ald);

    static bool attr_set = false;
    if (!attr_set) {
        cudaFuncSetAttribute(tf32_gemm_kernel,
                             cudaFuncAttributeMaxDynamicSharedMemorySize, 2 * BUFB);
        attr_set = true;
    }

    // edge-index width detection + CSR build
    detect_kernel<<<1, 32>>>((const int*)eidx);
    zero_kernel<<<(N_NODES + 255) / 256, 256>>>();
    count_kernel<<<(E_EDGES + 255) / 256, 256>>>(eidx);
    scan_kernel<<<1, 1024>>>();
    scatter_kernel<<<(E_EDGES + 255) / 256, 256>>>(eidx);

    // layer 1
    gemm1_kernel<<<N_NODES / G1N, 256>>>(x, W1, bufA);
    alpha_kernel<<<N_NODES, 256>>>(bufA, a_src1, a_dst1, als, ald);
    agg_kernel<<<N_NODES, 256>>>(bufA, als, ald, b1, bufB);

    // layer 2 (tf32 mma.sync GEMM)
    transpose_kernel<<<dim3(32, 32), dim3(32, 8)>>>(W2, w2t);
    dim3 g2(FEAT / 128, (N_NODES + 127) / 128);
    tf32_gemm_kernel<<<g2, 256, 2 * BUFB>>>(bufB, w2t, bufA, N_NODES);
    alpha_kernel<<<N_NODES, 256>>>(bufA, a_src2, a_dst2, als, ald);
    agg_kernel<<<N_NODES, 256>>>(bufA, als, ald, b2, bufB);

    // layer 3
    gemm3_kernel<<<(N_NODES * 32 + 255) / 256, 256>>>(bufB, W3, a_src3, a_dst3);
    agg3_kernel<<<(N_NODES * 32 + 255) / 256, 256>>>(b3, out);
}

// round 8
// speedup vs baseline: 2.4654x; 1.1996x over previous
#include <cuda_runtime.h>
#include <cuda_bf16.h>
#include <cstdint>

#define N_NODES 10000
#define E_EDGES 160000
#define IN_CH   14
#define HID     128
#define HEADS   8
#define OUT_CH  4
#define FEAT    (HEADS*HID)   // 1024

// ---------------- scratch (static device memory; no allocations) ----------------
__device__ float g_bufA[(size_t)N_NODES * FEAT];
__device__ float g_bufB[(size_t)N_NODES * FEAT];
__device__ float g_W2T[(size_t)FEAT * FEAT];
__device__ float g_als[N_NODES * HEADS];
__device__ float g_ald[N_NODES * HEADS];
__device__ float g_h3[N_NODES * OUT_CH];
__device__ float g_als3[N_NODES];
__device__ float g_ald3[N_NODES];
__device__ int   g_deg[N_NODES];
__device__ int   g_cursor[N_NODES];
__device__ int   g_rowptr[N_NODES + 1];
__device__ int   g_srcs[E_EDGES];
__device__ int   g_is64;

// ---------------- small PTX helpers ----------------
__device__ __forceinline__ uint32_t smem_u32(const void* p) {
    uint32_t a;
    asm("{ .reg .u64 t; cvta.to.shared.u64 t, %1; cvt.u32.u64 %0, t; }" : "=r"(a) : "l"(p));
    return a;
}

__device__ __forceinline__ void cp_async16(uint32_t s, const void* g, bool pred) {
    int sz = pred ? 16 : 0;
    asm volatile("cp.async.cg.shared.global [%0], [%1], 16, %2;\n"
                 :: "r"(s), "l"(g), "r"(sz) : "memory");
}
#define CP_COMMIT()  asm volatile("cp.async.commit_group;" ::: "memory")
#define CP_WAIT0()   asm volatile("cp.async.wait_group 0;" ::: "memory")

__device__ __forceinline__ uint32_t f2tf32(float f) {
    uint32_t r;
    asm("cvt.rna.tf32.f32 %0, %1;" : "=r"(r) : "f"(f));
    return r;
}

__device__ __forceinline__ void mma_tf32(float* c, const uint32_t* a, uint32_t b0, uint32_t b1) {
    asm volatile(
        "mma.sync.aligned.m16n8k8.row.col.f32.tf32.tf32.f32 "
        "{%0,%1,%2,%3}, {%4,%5,%6,%7}, {%8,%9}, {%0,%1,%2,%3};"
        : "+f"(c[0]), "+f"(c[1]), "+f"(c[2]), "+f"(c[3])
        : "r"(a[0]), "r"(a[1]), "r"(a[2]), "r"(a[3]), "r"(b0), "r"(b1));
}

__device__ __forceinline__ float leaky(float e) {
    return e > 0.f ? e : 0.2f * e;
}

// ---------------- edge index access (int32 vs int64 detected at runtime) --------
__device__ __forceinline__ int edge_val(const void* idx, int is64, long i) {
    if (is64) return (int)((const long long*)idx)[i];
    return ((const int*)idx)[i];
}

__global__ void detect_kernel(const int* p) {
    if (threadIdx.x == 0 && blockIdx.x == 0) {
        int is64 = 1;
        for (int i = 0; i < 64; i++) {
            if (p[2*i + 1] != 0) { is64 = 0; break; }
        }
        g_is64 = is64;
    }
}

// ---------------- CSR build ----------------
__global__ void zero_kernel() {
    int i = blockIdx.x * blockDim.x + threadIdx.x;
    if (i < N_NODES) { g_deg[i] = 0; g_cursor[i] = 0; }
}

__global__ void count_kernel(const void* idx) {
    int e = blockIdx.x * blockDim.x + threadIdx.x;
    if (e < E_EDGES) {
        int f = g_is64;
        int d = edge_val(idx, f, (long)E_EDGES + e);
        atomicAdd(&g_deg[d], 1);
    }
}

// shuffle-based scan: 1024 threads, 10 elems/thread, 2 barriers
__global__ void scan_kernel() {
    __shared__ int wsum[32];
    int t = threadIdx.x, lane = t & 31, w = t >> 5;
    const int CH = (N_NODES + 1023) / 1024;  // 10
    int base = t * CH;
    int s = 0;
#pragma unroll
    for (int i = 0; i < CH; i++) {
        int idx = base + i;
        if (idx < N_NODES) s += g_deg[idx];
    }
    int v = s;
#pragma unroll
    for (int off = 1; off < 32; off <<= 1) {
        int u = __shfl_up_sync(~0u, v, off);
        if (lane >= off) v += u;
    }
    if (lane == 31) wsum[w] = v;
    __syncthreads();
    if (w == 0) {
        int x = wsum[lane];
#pragma unroll
        for (int off = 1; off < 32; off <<= 1) {
            int u = __shfl_up_sync(~0u, x, off);
            if (lane >= off) x += u;
        }
        wsum[lane] = x;
    }
    __syncthreads();
    int excl = v - s + (w > 0 ? wsum[w - 1] : 0);
    int run = excl;
#pragma unroll
    for (int i = 0; i < CH; i++) {
        int idx = base + i;
        if (idx < N_NODES) { g_rowptr[idx] = run; run += g_deg[idx]; }
    }
    if (t == 1023) g_rowptr[N_NODES] = run;
}

__global__ void scatter_kernel(const void* idx) {
    int e = blockIdx.x * blockDim.x + threadIdx.x;
    if (e < E_EDGES) {
        int f = g_is64;
        int s = edge_val(idx, f, e);
        int d = edge_val(idx, f, (long)E_EDGES + e);
        int pos = g_rowptr[d] + atomicAdd(&g_cursor[d], 1);
        g_srcs[pos] = s;
    }
}

// ---------------- Layer-1 GEMM: [N,14] @ [14,1024], 16 nodes per block -----------
#define G1N 16
__global__ __launch_bounds__(256) void gemm1_kernel(const float* __restrict__ x,
                                                    const float* __restrict__ W1,
                                                    float* __restrict__ h) {
    __shared__ float xs[G1N * IN_CH];
    int nb = blockIdx.x * G1N;
    int t = threadIdx.x;
    if (t < G1N * IN_CH) xs[t] = x[nb * IN_CH + t];
    __syncthreads();
#pragma unroll
    for (int j = 0; j < 4; j++) {
        int c = t + j * 256;
        float w[IN_CH];
#pragma unroll
        for (int k = 0; k < IN_CH; k++) w[k] = W1[k * FEAT + c];
        for (int n = 0; n < G1N; n++) {
            float acc = 0.f;
#pragma unroll
            for (int k = 0; k < IN_CH; k++) acc += xs[n * IN_CH + k] * w[k];
            h[(size_t)(nb + n) * FEAT + c] = acc;
        }
    }
}

// ---------------- W2 transpose + tf32 pre-round: W2T[n][k] = rna(W2[k][n]) -------
__global__ __launch_bounds__(256) void transpose_kernel(const float* __restrict__ W,
                                                        float* __restrict__ WT) {
    __shared__ float t[32][33];
    int bx = blockIdx.x * 32, by = blockIdx.y * 32;
    int x = bx + threadIdx.x;
    int y = by + threadIdx.y;
#pragma unroll
    for (int j = 0; j < 32; j += 8) t[threadIdx.y + j][threadIdx.x] = W[(size_t)(y + j) * FEAT + x];
    __syncthreads();
    int x2 = by + threadIdx.x;
    int y2 = bx + threadIdx.y;
#pragma unroll
    for (int j = 0; j < 32; j += 8)
        WT[(size_t)(y2 + j) * FEAT + x2] = __uint_as_float(f2tf32(t[threadIdx.x][threadIdx.y + j]));
}

// ---------------- attention logits: als/ald [N,8] ----------------
__global__ __launch_bounds__(256) void alpha_kernel(const float* __restrict__ h,
                                                    const float* __restrict__ asrc,
                                                    const float* __restrict__ adst,
                                                    float* __restrict__ als,
                                                    float* __restrict__ ald) {
    int n = blockIdx.x;
    int t = threadIdx.x, w = t >> 5, lane = t & 31;
    const float* hr = h + (size_t)n * FEAT + w * HID;
    float ss = 0.f, sd = 0.f;
#pragma unroll
    for (int c = lane; c < HID; c += 32) {
        float v = hr[c];
        ss += v * asrc[w * HID + c];
        sd += v * adst[w * HID + c];
    }
#pragma unroll
    for (int off = 16; off; off >>= 1) {
        ss += __shfl_xor_sync(~0u, ss, off);
        sd += __shfl_xor_sync(~0u, sd, off);
    }
    if (lane == 0) { als[n * HEADS + w] = ss; ald[n * HEADS + w] = sd; }
}

// ---------------- fused per-node softmax + aggregate (heads=8, C=128) -----------
// round_out != 0: store tf32-rounded output (bit-identical to in-GEMM rounding)
__global__ __launch_bounds__(256) void agg_kernel(const float* __restrict__ h,
                                                  const float* __restrict__ als,
                                                  const float* __restrict__ ald,
                                                  const float* __restrict__ bias,
                                                  float* __restrict__ out,
                                                  int round_out) {
    int n = blockIdx.x;
    int t = threadIdx.x, w = t >> 5, lane = t & 31;
    __shared__ float s_alpha[HEADS][32];
    __shared__ int   s_src[32];

    int start = g_rowptr[n];
    int cnt   = g_rowptr[n + 1] - start;   // self-loop added implicitly at i==cnt

    float aldn = ald[n * HEADS + w];

    // single-pass online softmax stats (strided over edges)
    float m = -1e30f, z = 0.f;
    for (int i = lane; i <= cnt; i += 32) {
        int s = (i < cnt) ? g_srcs[start + i] : n;
        float e = leaky(als[s * HEADS + w] + aldn);
        float mn = fmaxf(m, e);
        z = z * expf(m - mn) + expf(e - mn);
        m = mn;
    }
#pragma unroll
    for (int off = 16; off; off >>= 1) {
        float mo = __shfl_xor_sync(~0u, m, off);
        float zo = __shfl_xor_sync(~0u, z, off);
        float mn = fmaxf(m, mo);
        z = z * expf(m - mn) + zo * expf(mo - mn);
        m = mn;
    }
    float iz = 1.f / (z + 1e-16f);

    // chunked aggregate: per-warp alpha precompute in smem, broadcast consume
    float4 acc = make_float4(0.f, 0.f, 0.f, 0.f);
    const int cbase = w * HID + lane * 4;
    for (int base = 0; base <= cnt; base += 32) {
        int i = base + lane;
        int s = n;
        float a = 0.f;
        if (i <= cnt) {
            if (i < cnt) s = g_srcs[start + i];
            float e = leaky(als[s * HEADS + w] + aldn);
            a = expf(e - m) * iz;
        }
        s_alpha[w][lane] = a;
        if (w == 0) s_src[lane] = s;
        __syncthreads();
        int lim = min(32, cnt + 1 - base);
        for (int j = 0; j < lim; j++) {
            float alpha = s_alpha[w][j];
            int sj = s_src[j];
            float4 hv = *(const float4*)&h[(size_t)sj * FEAT + cbase];
            acc.x += alpha * hv.x; acc.y += alpha * hv.y;
            acc.z += alpha * hv.z; acc.w += alpha * hv.w;
        }
        __syncthreads();
    }
    float4 b4 = *(const float4*)&bias[cbase];
    acc.x = fmaxf(acc.x + b4.x, 0.f);
    acc.y = fmaxf(acc.y + b4.y, 0.f);
    acc.z = fmaxf(acc.z + b4.z, 0.f);
    acc.w = fmaxf(acc.w + b4.w, 0.f);
    if (round_out) {
        acc.x = __uint_as_float(f2tf32(acc.x));
        acc.y = __uint_as_float(f2tf32(acc.y));
        acc.z = __uint_as_float(f2tf32(acc.z));
        acc.w = __uint_as_float(f2tf32(acc.w));
    }
    *(float4*)&out[(size_t)n * FEAT + cbase] = acc;
}

// ---------------- tf32 mma.sync GEMM: C[M,1024] = A[M,1024] @ W2, BT[n][k] -------
// Inputs pre-rounded to tf32; mainloop is raw LDS + HMMA only.
#define LDA  36                       // floats per smem row (32 + 4 pad)
#define TBUF (128 * LDA * 4)          // bytes per tile (18432)
#define BUFB (2 * TBUF)               // A+B per stage (36864)
#define NIT  32                       // 1024 / 32

__device__ __forceinline__ void load_tiles_async(
    const float* __restrict__ A, const float* __restrict__ BT,
    uint32_t sA, uint32_t sB, int row0, int n0, int k0, int M, int tid)
{
#pragma unroll
    for (int j = 0; j < 4; j++) {
        int f = tid + j * 256;            // 0..1023
        int r = f >> 3;                   // 0..127
        int c = f & 7;                    // float4 chunk
        uint32_t so = (uint32_t)(r * LDA + c * 4) * 4;
        bool ok = (row0 + r) < M;
        int ar = ok ? (row0 + r) : 0;
        cp_async16(sA + so, A  + (size_t)ar * FEAT + k0 + c * 4, ok);
        cp_async16(sB + so, BT + (size_t)(n0 + r) * FEAT + k0 + c * 4, true);
    }
}

__global__ __launch_bounds__(256) void tf32_gemm_kernel(
    const float* __restrict__ A, const float* __restrict__ BT,
    float* __restrict__ C, int M)
{
    extern __shared__ char dsm[];
    const uint32_t sbase = smem_u32(dsm);
    int tid = threadIdx.x;
    int wid = tid >> 5, lane = tid & 31;
    int grp = lane >> 2, tig = lane & 3;
    int wm = (wid & 1) * 64;
    int wn = (wid >> 1) * 32;
    int row0 = blockIdx.y * 128, n0 = blockIdx.x * 128;

    float acc[4][4][4];
#pragma unroll
    for (int i = 0; i < 4; i++)
#pragma unroll
        for (int j = 0; j < 4; j++)
#pragma unroll
            for (int k = 0; k < 4; k++) acc[i][j][k] = 0.f;

    load_tiles_async(A, BT, sbase, sbase + TBUF, row0, n0, 0, M, tid);
    CP_COMMIT();

    for (int it = 0; it < NIT; it++) {
        CP_WAIT0();
        __syncthreads();
        int cb = it & 1;
        if (it + 1 < NIT) {
            uint32_t nb = sbase + (cb ^ 1) * BUFB;
            load_tiles_async(A, BT, nb, nb + TBUF, row0, n0, (it + 1) * 32, M, tid);
            CP_COMMIT();
        }
        const uint32_t* As = (const uint32_t*)(dsm + cb * BUFB);
        const uint32_t* Bs = (const uint32_t*)(dsm + cb * BUFB + TBUF);
#pragma unroll
        for (int ks = 0; ks < 4; ks++) {
            int kk = ks * 8 + tig;
            uint32_t a[4][4];
#pragma unroll
            for (int mt = 0; mt < 4; mt++) {
                int r0 = wm + mt * 16 + grp;
                a[mt][0] = As[r0 * LDA + kk];
                a[mt][1] = As[(r0 + 8) * LDA + kk];
                a[mt][2] = As[r0 * LDA + kk + 4];
                a[mt][3] = As[(r0 + 8) * LDA + kk + 4];
            }
#pragma unroll
            for (int nt = 0; nt < 4; nt++) {
                int rn = wn + nt * 8 + grp;
                uint32_t b0 = Bs[rn * LDA + kk];
                uint32_t b1 = Bs[rn * LDA + kk + 4];
#pragma unroll
                for (int mt = 0; mt < 4; mt++) mma_tf32(acc[mt][nt], a[mt], b0, b1);
            }
        }
        __syncthreads();
    }

    // epilogue
#pragma unroll
    for (int mt = 0; mt < 4; mt++) {
        int gr = row0 + wm + mt * 16 + grp;
#pragma unroll
        for (int nt = 0; nt < 4; nt++) {
            int gc = n0 + wn + nt * 8 + 2 * tig;
            if (gr < M) {
                float2 v0 = make_float2(acc[mt][nt][0], acc[mt][nt][1]);
                *(float2*)&C[(size_t)gr * FEAT + gc] = v0;
            }
            if (gr + 8 < M) {
                float2 v1 = make_float2(acc[mt][nt][2], acc[mt][nt][3]);
                *(float2*)&C[(size_t)(gr + 8) * FEAT + gc] = v1;
            }
        }
    }
}

// ---------------- layer-3 GEMM + logits (warp per node) ----------------
__global__ __launch_bounds__(256) void gemm3_kernel(const float* __restrict__ h,
                                                    const float* __restrict__ W3,
                                                    const float* __restrict__ as3,
                                                    const float* __restrict__ ad3) {
    int gw = (blockIdx.x * blockDim.x + threadIdx.x) >> 5;
    int lane = threadIdx.x & 31;
    if (gw >= N_NODES) return;
    const float* hr = h + (size_t)gw * FEAT;
    float a0 = 0.f, a1 = 0.f, a2 = 0.f, a3 = 0.f;
    for (int k = lane; k < FEAT; k += 32) {
        float v = hr[k];
        a0 += v * W3[k * 4 + 0];
        a1 += v * W3[k * 4 + 1];
        a2 += v * W3[k * 4 + 2];
        a3 += v * W3[k * 4 + 3];
    }
#pragma unroll
    for (int off = 16; off; off >>= 1) {
        a0 += __shfl_xor_sync(~0u, a0, off);
        a1 += __shfl_xor_sync(~0u, a1, off);
        a2 += __shfl_xor_sync(~0u, a2, off);
        a3 += __shfl_xor_sync(~0u, a3, off);
    }
    if (lane == 0) {
        g_h3[gw * 4 + 0] = a0; g_h3[gw * 4 + 1] = a1;
        g_h3[gw * 4 + 2] = a2; g_h3[gw * 4 + 3] = a3;
        g_als3[gw] = a0 * as3[0] + a1 * as3[1] + a2 * as3[2] + a3 * as3[3];
        g_ald3[gw] = a0 * ad3[0] + a1 * ad3[1] + a2 * ad3[2] + a3 * ad3[3];
    }
}

// ---------------- layer-3 aggregation (warp per node, 1 head, C=4) --------------
__global__ __launch_bounds__(256) void agg3_kernel(const float* __restrict__ b3,
                                                   float* __restrict__ out) {
    int n = (blockIdx.x * blockDim.x + threadIdx.x) >> 5;
    int lane = threadIdx.x & 31;
    if (n >= N_NODES) return;
    int start = g_rowptr[n];
    int cnt   = g_rowptr[n + 1] - start;
    float aldn = g_ald3[n];
    float mx = -1e30f;
    for (int i = lane; i <= cnt; i += 32) {
        int s = (i < cnt) ? g_srcs[start + i] : n;
        mx = fmaxf(mx, leaky(g_als3[s] + aldn));
    }
#pragma unroll
    for (int off = 16; off; off >>= 1) mx = fmaxf(mx, __shfl_xor_sync(~0u, mx, off));
    float z = 0.f;
    float c0 = 0.f, c1 = 0.f, c2 = 0.f, c3 = 0.f;
    for (int i = lane; i <= cnt; i += 32) {
        int s = (i < cnt) ? g_srcs[start + i] : n;
        float e = leaky(g_als3[s] + aldn);
        float ex = expf(e - mx);
        z += ex;
        c0 += ex * g_h3[s * 4 + 0];
        c1 += ex * g_h3[s * 4 + 1];
        c2 += ex * g_h3[s * 4 + 2];
        c3 += ex * g_h3[s * 4 + 3];
    }
#pragma unroll
    for (int off = 16; off; off >>= 1) {
        z  += __shfl_xor_sync(~0u, z, off);
        c0 += __shfl_xor_sync(~0u, c0, off);
        c1 += __shfl_xor_sync(~0u, c1, off);
        c2 += __shfl_xor_sync(~0u, c2, off);
        c3 += __shfl_xor_sync(~0u, c3, off);
    }
    float iz = 1.f / (z + 1e-16f);
    if (lane == 0) {
        out[n * 4 + 0] = fmaxf(c0 * iz + b3[0], 0.f);
        out[n * 4 + 1] = fmaxf(c1 * iz + b3[1], 0.f);
        out[n * 4 + 2] = fmaxf(c2 * iz + b3[2], 0.f);
        out[n * 4 + 3] = fmaxf(c3 * iz + b3[3], 0.f);
    }
}

// ---------------- launch ----------------
extern "C" void kernel_launch(void* const* d_in, const int* in_sizes, int n_in,
                              void* d_out, int out_size) {
    const float* x      = (const float*)d_in[0];
    const void*  eidx   = d_in[1];
    const float* W1     = (const float*)d_in[2];
    const float* a_src1 = (const float*)d_in[3];
    const float* a_dst1 = (const float*)d_in[4];
    const float* b1     = (const float*)d_in[5];
    const float* W2     = (const float*)d_in[6];
    const float* a_src2 = (const float*)d_in[7];
    const float* a_dst2 = (const float*)d_in[8];
    const float* b2     = (const float*)d_in[9];
    const float* W3     = (const float*)d_in[10];
    const float* a_src3 = (const float*)d_in[11];
    const float* a_dst3 = (const float*)d_in[12];
    const float* b3     = (const float*)d_in[13];
    float* out = (float*)d_out;

    float* bufA; cudaGetSymbolAddress((void**)&bufA, g_bufA);
    float* bufB; cudaGetSymbolAddress((void**)&bufB, g_bufB);
    float* w2t;  cudaGetSymbolAddress((void**)&w2t,  g_W2T);
    float* als;  cudaGetSymbolAddress((void**)&als,  g_als);
    float* ald;  cudaGetSymbolAddress((void**)&ald,  g_ald);

    static bool attr_set = false;
    if (!attr_set) {
        cudaFuncSetAttribute(tf32_gemm_kernel,
                             cudaFuncAttributeMaxDynamicSharedMemorySize, 2 * BUFB);
        attr_set = true;
    }

    // edge-index width detection + CSR build
    detect_kernel<<<1, 32>>>((const int*)eidx);
    zero_kernel<<<(N_NODES + 255) / 256, 256>>>();
    count_kernel<<<(E_EDGES + 255) / 256, 256>>>(eidx);
    scan_kernel<<<1, 1024>>>();
    scatter_kernel<<<(E_EDGES + 255) / 256, 256>>>(eidx);

    // layer 1
    gemm1_kernel<<<N_NODES / G1N, 256>>>(x, W1, bufA);
    alpha_kernel<<<N_NODES, 256>>>(bufA, a_src1, a_dst1, als, ald);
    agg_kernel<<<N_NODES, 256>>>(bufA, als, ald, b1, bufB, 1);  // tf32-round for GEMM

    // layer 2 (tf32 mma.sync GEMM, pre-rounded inputs)
    transpose_kernel<<<dim3(32, 32), dim3(32, 8)>>>(W2, w2t);
    dim3 g2(FEAT / 128, (N_NODES + 127) / 128);
    tf32_gemm_kernel<<<g2, 256, 2 * BUFB>>>(bufB, w2t, bufA, N_NODES);
    alpha_kernel<<<N_NODES, 256>>>(bufA, a_src2, a_dst2, als, ald);
    agg_kernel<<<N_NODES, 256>>>(bufA, als, ald, b2, bufB, 0);

    // layer 3
    gemm3_kernel<<<(N_NODES * 32 + 255) / 256, 256>>>(bufB, W3, a_src3, a_dst3);
    agg3_kernel<<<(N_NODES * 32 + 255) / 256, 256>>>(b3, out);
}